// round 1
// baseline (speedup 1.0000x reference)
#include <cuda_runtime.h>

#define NN   100000
#define NE   1200000
#define DIM  64
#define NL   3
#define NG   256
#define RHID 128
#define ROUT 32

// Scratch (static __device__ globals: allocation-guard safe)
__device__ float d_agg[NN * DIM];            // 25.6 MB
__device__ float d_h[NL][NN * DIM];          // 76.8 MB
__device__ float d_g[NG * NL * DIM];         // 192 KB

// ---------------------------------------------------------------------------
// Zero kernels (reference device symbols directly; no symbol-address APIs)
// ---------------------------------------------------------------------------
__global__ void zero_agg_kernel() {
    int i = blockIdx.x * blockDim.x + threadIdx.x;
    if (i < NN * DIM / 4)
        reinterpret_cast<float4*>(d_agg)[i] = make_float4(0.f, 0.f, 0.f, 0.f);
}

__global__ void zero_g_kernel() {               // grid sized exactly: 192*256 = 49152
    int i = blockIdx.x * blockDim.x + threadIdx.x;
    d_g[i] = 0.f;
}

// ---------------------------------------------------------------------------
// Edge scatter: agg[dst] += h[src]. One thread per (edge, 4 dims).
// red.global.add.v4.f32 -> 4x fewer atomic ops than scalar atomicAdd.
// ---------------------------------------------------------------------------
__global__ void scatter_kernel(const float* __restrict__ x, int layer,
                               const int* __restrict__ src,
                               const int* __restrict__ dst) {
    const float* __restrict__ h = (layer == 0) ? x : d_h[layer - 1];
    unsigned idx = blockIdx.x * blockDim.x + threadIdx.x;
    if (idx >= NE * 16u) return;
    unsigned e  = idx >> 4;
    unsigned c4 = (idx & 15u) << 2;
    int s = src[e];
    int t = dst[e];
    float4 v = *reinterpret_cast<const float4*>(h + (size_t)s * DIM + c4);
    float* p = d_agg + (size_t)t * DIM + c4;
    asm volatile("red.global.add.v4.f32 [%0], {%1,%2,%3,%4};"
                 :: "l"(p), "f"(v.x), "f"(v.y), "f"(v.z), "f"(v.w)
                 : "memory");
}

// ---------------------------------------------------------------------------
// GIN update: h_next = relu(((1+eps)*h + agg) @ W + b)
// Block = 256 threads, 64 nodes. W and input tile staged in SMEM.
// Thread (node, cg) computes the 16 contiguous output cols [16*cg, 16*cg+16).
// Warp stores are fully coalesced (8 consecutive 256B node rows per warp).
// ---------------------------------------------------------------------------
__global__ void gin_update_kernel(const float* __restrict__ x,
                                  const float* __restrict__ gW,
                                  const float* __restrict__ gB,
                                  const float* __restrict__ eps,
                                  int layer) {
    __shared__ float Ws[DIM * DIM];      // 16 KB
    __shared__ float ins[64 * 65];       // padded rows, 16.25 KB

    const float* __restrict__ h_prev = (layer == 0) ? x : d_h[layer - 1];
    int t  = threadIdx.x;
    int n0 = blockIdx.x * 64;

    const float* W = gW + layer * DIM * DIM;
    for (int i = t; i < DIM * DIM; i += 256) Ws[i] = W[i];

    float e1 = 1.0f + eps[layer];
    for (int i = t; i < 64 * DIM; i += 256) {
        int node = i >> 6, col = i & 63;
        int n = n0 + node;
        float v = 0.f;
        if (n < NN) {
            size_t gi = (size_t)n * DIM + col;
            v = e1 * h_prev[gi] + d_agg[gi];
        }
        ins[node * 65 + col] = v;
    }
    __syncthreads();

    int node = t >> 2, cg = t & 3;
    float acc[16];
#pragma unroll
    for (int j = 0; j < 16; j++) acc[j] = gB[layer * DIM + cg * 16 + j];

    const float* ir = &ins[node * 65];
#pragma unroll
    for (int k = 0; k < DIM; k++) {
        float a = ir[k];
        const float* wr = &Ws[k * DIM + cg * 16];
#pragma unroll
        for (int j = 0; j < 16; j++) acc[j] = fmaf(a, wr[j], acc[j]);
    }

    int n = n0 + node;
    if (n < NN) {
        float4* op = reinterpret_cast<float4*>(&d_h[layer][(size_t)n * DIM + cg * 16]);
#pragma unroll
        for (int q = 0; q < 4; q++)
            op[q] = make_float4(fmaxf(acc[4*q+0], 0.f), fmaxf(acc[4*q+1], 0.f),
                                fmaxf(acc[4*q+2], 0.f), fmaxf(acc[4*q+3], 0.f));
    }
}

// ---------------------------------------------------------------------------
// Readout: g[b, l*64+d] = sum over nodes with graph_ids==b of h_l[n, d].
// graph_ids is SORTED -> segmented running sum: one atomic per
// (block, graph transition) instead of one per node.
// blockDim = 192 (thread t owns layer t/64, column t%64).
// ---------------------------------------------------------------------------
#define RO_CHUNK 512
__global__ void readout_kernel(const int* __restrict__ gid) {
    int t   = threadIdx.x;                  // 0..191
    int lay = t >> 6, col = t & 63;
    int n0  = blockIdx.x * RO_CHUNK;
    int nend = min(n0 + RO_CHUNK, NN);
    const float* __restrict__ hp = d_h[lay];

    float acc = 0.f;
    int cur = gid[n0];
    for (int n = n0; n < nend; n++) {
        int gi = gid[n];                    // broadcast load, uniform branch
        if (gi != cur) {
            atomicAdd(&d_g[cur * (NL * DIM) + t], acc);
            acc = 0.f;
            cur = gi;
        }
        acc += hp[(size_t)n * DIM + col];   // coalesced across warp
    }
    atomicAdd(&d_g[cur * (NL * DIM) + t], acc);
}

// ---------------------------------------------------------------------------
// Readout MLP: out = relu(g @ W1 + b1) @ W2 + b2.  One block per graph.
// ---------------------------------------------------------------------------
__global__ void mlp_kernel(const float* __restrict__ W1, const float* __restrict__ b1,
                           const float* __restrict__ W2, const float* __restrict__ b2,
                           float* __restrict__ out) {
    int b = blockIdx.x, t = threadIdx.x;    // 192 threads
    __shared__ float gv[NL * DIM];
    __shared__ float hid[RHID];

    gv[t] = d_g[b * (NL * DIM) + t];
    __syncthreads();

    if (t < RHID) {
        float acc = b1[t];
#pragma unroll 4
        for (int k = 0; k < NL * DIM; k++)
            acc = fmaf(gv[k], W1[k * RHID + t], acc);
        hid[t] = fmaxf(acc, 0.f);
    }
    __syncthreads();

    if (t < ROUT) {
        float acc = b2[t];
#pragma unroll 4
        for (int k = 0; k < RHID; k++)
            acc = fmaf(hid[k], W2[k * ROUT + t], acc);
        out[b * ROUT + t] = acc;
    }
}

// ---------------------------------------------------------------------------
extern "C" void kernel_launch(void* const* d_in, const int* in_sizes, int n_in,
                              void* d_out, int out_size) {
    const float* x   = (const float*)d_in[0];
    const float* gW  = (const float*)d_in[1];
    const float* gB  = (const float*)d_in[2];
    const float* eps = (const float*)d_in[3];
    const float* rW1 = (const float*)d_in[4];
    const float* rb1 = (const float*)d_in[5];
    const float* rW2 = (const float*)d_in[6];
    const float* rb2 = (const float*)d_in[7];
    const int*   src = (const int*)d_in[8];
    const int*   dst = (const int*)d_in[9];
    const int*   gid = (const int*)d_in[10];
    float* out = (float*)d_out;

    zero_g_kernel<<<192, 256>>>();

    for (int l = 0; l < NL; l++) {
        zero_agg_kernel<<<(NN * DIM / 4 + 255) / 256, 256>>>();
        scatter_kernel<<<(NE * 16 + 255) / 256, 256>>>(x, l, src, dst);
        gin_update_kernel<<<(NN + 63) / 64, 256>>>(x, gW, gB, eps, l);
    }

    readout_kernel<<<(NN + RO_CHUNK - 1) / RO_CHUNK, 192>>>(gid);
    mlp_kernel<<<NG, 192>>>(rW1, rb1, rW2, rb2, out);
}